// round 11
// baseline (speedup 1.0000x reference)
#include <cuda_runtime.h>

// AudioOnlySpecAugment
// X: (B=32, T=2048, D=1536) f32. First 256 dims pass through; last A=1280 are audio.
// Per batch b: 2 time-mask intervals over t, 2 freq-mask intervals over a.
// out[b,t,d] = X[b,t,d] (d<256); 0 if tmask[b,t] | fmask[b,d-256]; else X[b,t,d].

#define BATCH   32
#define SEQ_T   2048
#define DIM     1536
#define AUD     1280
#define VDIM    256
#define F4_PER_ROW (DIM / 4)   // 384
#define THREADS 128

// Per-batch mask params: [b*2+0] = {t0_0, tend_0, t0_1, tend_1}
//                        [b*2+1] = {f0_0, fend_0, f0_1, fend_1}
__device__ int4 g_params[BATCH * 2];

// One warp. Detects whether `lengths` was materialized as int32 or int64,
// then computes all interval endpoints with exact f32 reference semantics.
__global__ void spec_aug_params_kernel(const int* __restrict__ len_raw,
                                       const float* __restrict__ u_t,
                                       const float* __restrict__ u_t0,
                                       const float* __restrict__ u_f,
                                       const float* __restrict__ u_f0)
{
    const int b = threadIdx.x;   // 0..31

    // dtype sniff on the first 128 bytes (valid under both layouts):
    // int64 storage -> all 16 odd int32 words are 0 (values < 2^32).
    // int32 storage -> odd words are random lengths; all-zero is ~2048^-16.
    const int odd_word = len_raw[2 * (b & 15) + 1];
    const unsigned ball = __ballot_sync(0xFFFFFFFFu, odd_word == 0);
    const bool is_i64 = (ball == 0xFFFFFFFFu);

    const int len = is_i64 ? len_raw[2 * b] : len_raw[b];

    // --- time masks (TR = 0.2) ---
    const float max_t = floorf((float)len * 0.2f);
    int tp[4];
    #pragma unroll
    for (int n = 0; n < 2; n++) {
        const int tn  = (int)floorf(u_t[n * BATCH + b] * (max_t + 1.0f));
        const int rem = len - tn;
        const int t0  = (rem <= 0) ? 0
                      : (int)floorf(u_t0[n * BATCH + b] * ((float)rem + 1.0f));
        tp[n * 2]     = t0;
        tp[n * 2 + 1] = t0 + tn;
    }
    // --- freq masks ---
    // max_f = int(1280 * double(0.15)): product rounds to exactly 192.0 in
    // double (err 7.1e-15 < half-ulp 1.42e-14), so max_f = 192 and the
    // reference multiplier is (max_f + 1.0) = 193.0f.
    int fp[4];
    #pragma unroll
    for (int n = 0; n < 2; n++) {
        const int f   = (int)floorf(u_f[n * BATCH + b] * 193.0f);
        int f0m = AUD - f; if (f0m < 0) f0m = 0;
        const int f0  = (int)floorf(u_f0[n * BATCH + b] * ((float)f0m + 1.0f));
        fp[n * 2]     = f0;
        fp[n * 2 + 1] = f0 + f;
    }

    g_params[b * 2]     = make_int4(tp[0], tp[1], tp[2], tp[3]);
    g_params[b * 2 + 1] = make_int4(fp[0], fp[1], fp[2], fp[3]);
}

// One block per (b,t) row. 128 threads x 3 float4 = 1536 floats.
__global__ void __launch_bounds__(THREADS)
spec_aug_mask_kernel(const float4* __restrict__ X, float4* __restrict__ out)
{
    const int row = blockIdx.x;
    const int b   = row >> 11;            // T = 2048
    const int t   = row & (SEQ_T - 1);

    // Uniform per block -> warp-broadcast loads, L2-resident.
    const int4 tp = __ldg(&g_params[b * 2]);
    const int4 fq = __ldg(&g_params[b * 2 + 1]);
    const bool tm = (t >= tp.x && t < tp.y) || (t >= tp.z && t < tp.w);

    const float4* src = X   + (size_t)row * F4_PER_ROW;
    float4*       dst = out + (size_t)row * F4_PER_ROW;

    // Front-batch the loads (MLP_p1 = 3), then mask + store.
    float4 v[3];
    #pragma unroll
    for (int i = 0; i < 3; i++)
        v[i] = __ldg(src + threadIdx.x + i * THREADS);

    #pragma unroll
    for (int i = 0; i < 3; i++) {
        const int c4 = threadIdx.x + i * THREADS;   // 0..383
        const int d  = c4 * 4;
        if (d >= VDIM) {                            // audio region
            if (tm) {
                v[i].x = 0.0f; v[i].y = 0.0f; v[i].z = 0.0f; v[i].w = 0.0f;
            } else {
                const int a = d - VDIM;
                if ((a     >= fq.x && a     < fq.y) || (a     >= fq.z && a     < fq.w)) v[i].x = 0.0f;
                if ((a + 1 >= fq.x && a + 1 < fq.y) || (a + 1 >= fq.z && a + 1 < fq.w)) v[i].y = 0.0f;
                if ((a + 2 >= fq.x && a + 2 < fq.y) || (a + 2 >= fq.z && a + 2 < fq.w)) v[i].z = 0.0f;
                if ((a + 3 >= fq.x && a + 3 < fq.y) || (a + 3 >= fq.z && a + 3 < fq.w)) v[i].w = 0.0f;
            }
        }
        dst[c4] = v[i];
    }
}

extern "C" void kernel_launch(void* const* d_in, const int* in_sizes, int n_in,
                              void* d_out, int out_size)
{
    const float4* X    = (const float4*)d_in[0];
    const int*    lenr = (const int*)d_in[1];      // int32 OR int64 — sniffed on device
    const float*  u_t  = (const float*)d_in[2];
    const float*  u_t0 = (const float*)d_in[3];
    const float*  u_f  = (const float*)d_in[4];
    const float*  u_f0 = (const float*)d_in[5];
    float4*       out  = (float4*)d_out;

    spec_aug_params_kernel<<<1, BATCH>>>(lenr, u_t, u_t0, u_f, u_f0);
    spec_aug_mask_kernel<<<BATCH * SEQ_T, THREADS>>>(X, out);
}

// round 13
// speedup vs baseline: 1.0144x; 1.0144x over previous
#include <cuda_runtime.h>

// AudioOnlySpecAugment — fully fused single kernel.
// X: (B=32, T=2048, D=1536) f32. First 256 dims pass through; last A=1280 are audio.
// Per batch b: 2 time-mask intervals over t, 2 freq-mask intervals over a.
// out[b,t,d] = X[b,t,d] (d<256); 0 if tmask[b,t] | fmask[b,d-256]; else X[b,t,d].
//
// Param math (~40 FLOPs on L2-hot scalars) is recomputed by warp 0 of every
// block while the block's 3x LDG.128 data loads are in flight (DRAM latency
// ~577 cyc fully hides it + the single __syncthreads).

#define BATCH   32
#define SEQ_T   2048
#define DIM     1536
#define AUD     1280
#define VDIM    256
#define F4_PER_ROW (DIM / 4)   // 384
#define THREADS 128

__global__ void __launch_bounds__(THREADS)
spec_aug_fused_kernel(const float4* __restrict__ X,
                      const int*    __restrict__ len_raw,   // int32 or int64, sniffed
                      const float*  __restrict__ u_t,
                      const float*  __restrict__ u_t0,
                      const float*  __restrict__ u_f,
                      const float*  __restrict__ u_f0,
                      float4*       __restrict__ out)
{
    __shared__ int p[8];   // {t0_0,tend_0,t0_1,tend_1, f0_0,fend_0,f0_1,fend_1}

    const int row = blockIdx.x;          // row = b*T + t
    const int b   = row >> 11;           // T = 2048
    const int t   = row & (SEQ_T - 1);

    const float4* src = X   + (size_t)row * F4_PER_ROW;
    float4*       dst = out + (size_t)row * F4_PER_ROW;

    // Kick off the streaming loads first (evict-first: data is touched once).
    float4 v0 = __ldcs(src + threadIdx.x);
    float4 v1 = __ldcs(src + threadIdx.x + THREADS);
    float4 v2 = __ldcs(src + threadIdx.x + 2 * THREADS);

    if (threadIdx.x < 32) {
        // dtype sniff on the first 128 bytes (valid under both layouts):
        // int64 storage -> all 16 odd int32 words are 0 (values < 2^32).
        // int32 storage -> odd words are random lengths; all-zero ~ 2048^-16.
        const int odd_word = len_raw[2 * (threadIdx.x & 15) + 1];
        const unsigned ball = __ballot_sync(0xFFFFFFFFu, odd_word == 0);
        const bool is_i64 = (ball == 0xFFFFFFFFu);

        if (threadIdx.x == 0) {
            const int len = is_i64 ? len_raw[2 * b] : len_raw[b];

            // --- time masks (TR = 0.2) ---
            const float max_t = floorf((float)len * 0.2f);
            #pragma unroll
            for (int n = 0; n < 2; n++) {
                const int tn  = (int)floorf(u_t[n * BATCH + b] * (max_t + 1.0f));
                const int rem = len - tn;
                const int t0  = (rem <= 0) ? 0
                              : (int)floorf(u_t0[n * BATCH + b] * ((float)rem + 1.0f));
                p[n * 2]     = t0;
                p[n * 2 + 1] = t0 + tn;
            }
            // --- freq masks ---
            // max_f = int(1280 * double(0.15)) = 192 (product rounds to exactly
            // 192.0 in double), so the multiplier is (max_f + 1.0) = 193.0f.
            #pragma unroll
            for (int n = 0; n < 2; n++) {
                const int f   = (int)floorf(u_f[n * BATCH + b] * 193.0f);
                int f0m = AUD - f; if (f0m < 0) f0m = 0;
                const int f0  = (int)floorf(u_f0[n * BATCH + b] * ((float)f0m + 1.0f));
                p[4 + n * 2]     = f0;
                p[4 + n * 2 + 1] = f0 + f;
            }
        }
    }
    __syncthreads();

    const bool tm  = (t >= p[0] && t < p[1]) || (t >= p[2] && t < p[3]);
    const int  f00 = p[4], f01 = p[5], f10 = p[6], f11 = p[7];

    float4 v[3] = {v0, v1, v2};

    #pragma unroll
    for (int i = 0; i < 3; i++) {
        const int c4 = threadIdx.x + i * THREADS;   // 0..383
        const int d  = c4 * 4;
        if (d >= VDIM) {                            // audio region
            if (tm) {
                v[i].x = 0.0f; v[i].y = 0.0f; v[i].z = 0.0f; v[i].w = 0.0f;
            } else {
                const int a = d - VDIM;
                if ((a     >= f00 && a     < f01) || (a     >= f10 && a     < f11)) v[i].x = 0.0f;
                if ((a + 1 >= f00 && a + 1 < f01) || (a + 1 >= f10 && a + 1 < f11)) v[i].y = 0.0f;
                if ((a + 2 >= f00 && a + 2 < f01) || (a + 2 >= f10 && a + 2 < f11)) v[i].z = 0.0f;
                if ((a + 3 >= f00 && a + 3 < f01) || (a + 3 >= f10 && a + 3 < f11)) v[i].w = 0.0f;
            }
        }
        __stcs(dst + c4, v[i]);   // evict-first store: output never re-read
    }
}

extern "C" void kernel_launch(void* const* d_in, const int* in_sizes, int n_in,
                              void* d_out, int out_size)
{
    const float4* X    = (const float4*)d_in[0];
    const int*    lenr = (const int*)d_in[1];      // int32 OR int64 — sniffed on device
    const float*  u_t  = (const float*)d_in[2];
    const float*  u_t0 = (const float*)d_in[3];
    const float*  u_f  = (const float*)d_in[4];
    const float*  u_f0 = (const float*)d_in[5];
    float4*       out  = (float4*)d_out;

    spec_aug_fused_kernel<<<BATCH * SEQ_T, THREADS>>>(X, lenr, u_t, u_t0, u_f, u_f0, out);
}

// round 16
// speedup vs baseline: 1.0153x; 1.0008x over previous
#include <cuda_runtime.h>

// AudioOnlySpecAugment — single fused kernel, barrier-free.
// X: (B=32, T=2048, D=1536) f32. First 256 dims pass through; last A=1280 are audio.
// Per batch b: 2 time-mask intervals over t, 2 freq-mask intervals over a.
// out[b,t,d] = X[b,t,d] (d<256); 0 if tmask[b,t] | fmask[b,d-256]; else X[b,t,d].
//
// Param math is recomputed redundantly by EVERY thread from warp-uniform
// (HW-broadcast) L2-hot scalar loads, all issued independently (MLP=9) right
// after the 3 streaming LDG.128s. One ~234-cyc L2 round trip + ~40 FLOPs,
// fully hidden behind the ~577-cyc DRAM latency of the data loads.
// No shared memory, no __syncthreads, no serialized chain.

#define BATCH   32
#define SEQ_T   2048
#define DIM     1536
#define AUD     1280
#define VDIM    256
#define F4_PER_ROW (DIM / 4)   // 384
#define THREADS 128

__global__ void __launch_bounds__(THREADS)
spec_aug_fused_kernel(const float4* __restrict__ X,
                      const int*    __restrict__ len_raw,   // int32 or int64, sniffed
                      const float*  __restrict__ u_t,
                      const float*  __restrict__ u_t0,
                      const float*  __restrict__ u_f,
                      const float*  __restrict__ u_f0,
                      float4*       __restrict__ out)
{
    const int row  = blockIdx.x;          // row = b*T + t
    const int b    = row >> 11;           // T = 2048
    const int t    = row & (SEQ_T - 1);
    const int lane = threadIdx.x & 31;

    const float4* src = X   + (size_t)row * F4_PER_ROW;
    float4*       dst = out + (size_t)row * F4_PER_ROW;

    // 1) Streaming loads first (evict-first: touched exactly once).
    float4 v0 = __ldcs(src + threadIdx.x);
    float4 v1 = __ldcs(src + threadIdx.x + THREADS);
    float4 v2 = __ldcs(src + threadIdx.x + 2 * THREADS);

    // 2) All param scalars as independent broadcast loads (no dependency chain).
    //    dtype sniff: int64 storage -> all 16 odd int32 words of the first
    //    128 bytes are 0; int32 storage -> random lengths (all-zero ~2048^-16).
    //    Load BOTH length candidates up front so the ballot gates only a select.
    const int   odd   = __ldg(len_raw + 2 * (lane & 15) + 1);
    const int   lenA  = __ldg(len_raw + 2 * b);            // if int64 storage
    const int   lenB  = __ldg(len_raw + b);                // if int32 storage
    const float ut_0  = __ldg(u_t  + b);
    const float ut_1  = __ldg(u_t  + BATCH + b);
    const float ut0_0 = __ldg(u_t0 + b);
    const float ut0_1 = __ldg(u_t0 + BATCH + b);
    const float uf_0  = __ldg(u_f  + b);
    const float uf_1  = __ldg(u_f  + BATCH + b);
    const float uf0_0 = __ldg(u_f0 + b);
    const float uf0_1 = __ldg(u_f0 + BATCH + b);

    const bool is_i64 = (__ballot_sync(0xFFFFFFFFu, odd == 0) == 0xFFFFFFFFu);
    const int  len    = is_i64 ? lenA : lenB;

    // 3) Uniform param math (every thread, exact f32 reference semantics).
    // --- time masks (TR = 0.2) ---
    const float max_t = floorf((float)len * 0.2f);
    const int tn0  = (int)floorf(ut_0 * (max_t + 1.0f));
    const int rem0 = len - tn0;
    const int t00  = (rem0 <= 0) ? 0 : (int)floorf(ut0_0 * ((float)rem0 + 1.0f));
    const int tn1  = (int)floorf(ut_1 * (max_t + 1.0f));
    const int rem1 = len - tn1;
    const int t10  = (rem1 <= 0) ? 0 : (int)floorf(ut0_1 * ((float)rem1 + 1.0f));
    // --- freq masks: max_f = int(1280 * double(0.15)) = 192 -> multiplier 193.0f ---
    const int fa   = (int)floorf(uf_0 * 193.0f);
    int f0mA = AUD - fa; if (f0mA < 0) f0mA = 0;
    const int f00  = (int)floorf(uf0_0 * ((float)f0mA + 1.0f));
    const int f01  = f00 + fa;
    const int fb   = (int)floorf(uf_1 * 193.0f);
    int f0mB = AUD - fb; if (f0mB < 0) f0mB = 0;
    const int f10  = (int)floorf(uf0_1 * ((float)f0mB + 1.0f));
    const int f11  = f10 + fb;

    const bool tm = (t >= t00 && t < t00 + tn0) || (t >= t10 && t < t10 + tn1);

    // 4) Mask + store.
    float4 v[3] = {v0, v1, v2};
    #pragma unroll
    for (int i = 0; i < 3; i++) {
        const int c4 = threadIdx.x + i * THREADS;   // 0..383
        const int d  = c4 * 4;
        if (d >= VDIM) {                            // audio region
            if (tm) {
                v[i].x = 0.0f; v[i].y = 0.0f; v[i].z = 0.0f; v[i].w = 0.0f;
            } else {
                const int a = d - VDIM;
                if ((a     >= f00 && a     < f01) || (a     >= f10 && a     < f11)) v[i].x = 0.0f;
                if ((a + 1 >= f00 && a + 1 < f01) || (a + 1 >= f10 && a + 1 < f11)) v[i].y = 0.0f;
                if ((a + 2 >= f00 && a + 2 < f01) || (a + 2 >= f10 && a + 2 < f11)) v[i].z = 0.0f;
                if ((a + 3 >= f00 && a + 3 < f01) || (a + 3 >= f10 && a + 3 < f11)) v[i].w = 0.0f;
            }
        }
        __stcs(dst + c4, v[i]);   // evict-first store: output never re-read
    }
}

extern "C" void kernel_launch(void* const* d_in, const int* in_sizes, int n_in,
                              void* d_out, int out_size)
{
    const float4* X    = (const float4*)d_in[0];
    const int*    lenr = (const int*)d_in[1];      // int32 OR int64 — sniffed on device
    const float*  u_t  = (const float*)d_in[2];
    const float*  u_t0 = (const float*)d_in[3];
    const float*  u_f  = (const float*)d_in[4];
    const float*  u_f0 = (const float*)d_in[5];
    float4*       out  = (float4*)d_out;

    spec_aug_fused_kernel<<<BATCH * SEQ_T, THREADS>>>(X, lenr, u_t, u_t0, u_f, u_f0, out);
}